// round 5
// baseline (speedup 1.0000x reference)
#include <cuda_runtime.h>
#include <cstdint>

// ----------------------------------------------------------------------------
// Decoder_61237643706389 — fused trilinear MLP decoder, fp32x2 (FFMA2) path.
// Round 4: back to r2 shape (4 points x 8 corners = 32 units, 96 threads,
// per-thread tile 4ch x 8u, 4 blocks/SM = 12 warps) + explicit software
// pipelining of the k-loop (prefetch w,h one step ahead) to hide LDS/LDG
// latency inside each warp (r2/r3 were latency-bound: issue 38%/27%).
// ----------------------------------------------------------------------------

#define G        32
#define NBATCH   2
#define CCH      96
#define NPTS     32768          // points per batch (32^3)
#define OUTC     45
#define NCOORD   78
#define NP       4              // points per block
#define NU       32             // units per block (NP * 8 corners)
#define PAD      36             // row stride in floats (32 units + 4 pad, 144B)
#define THREADS  96

// Transposed context features: [B][x][y][z][C], contiguous C — 25.2 MB scratch.
__device__ float g_cvt[NBATCH * NPTS * CCH];

typedef unsigned long long u64;

__device__ __forceinline__ u64 pack2(float lo, float hi) {
    u64 r; asm("mov.b64 %0, {%1, %2};" : "=l"(r) : "f"(lo), "f"(hi)); return r;
}
__device__ __forceinline__ void unpack2(u64 v, float& lo, float& hi) {
    asm("mov.b64 {%0, %1}, %2;" : "=f"(lo), "=f"(hi) : "l"(v));
}
__device__ __forceinline__ u64 ffma2(u64 a, u64 b, u64 c) {
    u64 d; asm("fma.rn.f32x2 %0, %1, %2, %3;" : "=l"(d) : "l"(a), "l"(b), "l"(c));
    return d;
}
__device__ __forceinline__ float silu_f(float x) {
    return x / (1.0f + __expf(-x));
}

// ---------------------------------------------------------------------------
// Transpose context_v [B,C,S] -> g_cvt [B,S,C], S = 32^3. Tiled via SMEM.
// ---------------------------------------------------------------------------
__global__ void transpose_ctx(const float* __restrict__ src) {
    __shared__ float tile[CCH][65];          // pad 64->65 kills bank conflicts
    int bs = blockIdx.x;                     // 0 .. NBATCH*512-1
    int b  = bs >> 9;
    int s0 = (bs & 511) * 64;
    for (int idx = threadIdx.x; idx < CCH * 64; idx += blockDim.x) {
        int c = idx >> 6, so = idx & 63;
        tile[c][so] = src[((long)(b * CCH + c) << 15) + s0 + so];
    }
    __syncthreads();
    for (int idx = threadIdx.x; idx < CCH * 64; idx += blockDim.x) {
        int so = idx / CCH, c = idx % CCH;
        g_cvt[(((long)b << 15) + s0 + so) * CCH + c] = tile[c][so];
    }
}

// ---------------------------------------------------------------------------
// Compute one k-step from pre-loaded operands: 4 channels x 8 units = 16 FFMA2.
// ---------------------------------------------------------------------------
__device__ __forceinline__ void kcompute(float4 w4, double2 hA, double2 hB,
                                         u64 (&acc)[4][4]) {
    u64 h0 = __double_as_longlong(hA.x);
    u64 h1 = __double_as_longlong(hA.y);
    u64 h2 = __double_as_longlong(hB.x);
    u64 h3 = __double_as_longlong(hB.y);
    u64 wd;
    wd = pack2(w4.x, w4.x);
    acc[0][0] = ffma2(h0, wd, acc[0][0]); acc[0][1] = ffma2(h1, wd, acc[0][1]);
    acc[0][2] = ffma2(h2, wd, acc[0][2]); acc[0][3] = ffma2(h3, wd, acc[0][3]);
    wd = pack2(w4.y, w4.y);
    acc[1][0] = ffma2(h0, wd, acc[1][0]); acc[1][1] = ffma2(h1, wd, acc[1][1]);
    acc[1][2] = ffma2(h2, wd, acc[1][2]); acc[1][3] = ffma2(h3, wd, acc[1][3]);
    wd = pack2(w4.z, w4.z);
    acc[2][0] = ffma2(h0, wd, acc[2][0]); acc[2][1] = ffma2(h1, wd, acc[2][1]);
    acc[2][2] = ffma2(h2, wd, acc[2][2]); acc[2][3] = ffma2(h3, wd, acc[2][3]);
    wd = pack2(w4.w, w4.w);
    acc[3][0] = ffma2(h0, wd, acc[3][0]); acc[3][1] = ffma2(h1, wd, acc[3][1]);
    acc[3][2] = ffma2(h2, wd, acc[3][2]); acc[3][3] = ffma2(h3, wd, acc[3][3]);
}

// Linear layer (K1 rows from s1, optional K2 rows from s2) + silu + residual.
// Activations layout: [96 channels][PAD units].
// Thread (jg, ug) owns channels 4jg..4jg+3, units 8ug..8ug+7.
// Software-pipelined: w(k+1)/h(k+1) loads are issued before the 16 FFMA2 of
// step k, giving ~32 fma-pipe cycles of cover for the 29-cyc LDS latency.
template <int K1, int K2, bool RES>
__device__ __forceinline__ void mlp_layer(const float* __restrict__ W,
                                          const float* __restrict__ Bv,
                                          const float* s1, const float* s2,
                                          float* dst, const float* resid,
                                          int jg, int ug) {
    u64 acc[4][4];
#pragma unroll
    for (int ch = 0; ch < 4; ++ch) {
        float bv = __ldg(Bv + 4 * jg + ch);
        u64 bb = pack2(bv, bv);
        acc[ch][0] = bb; acc[ch][1] = bb; acc[ch][2] = bb; acc[ch][3] = bb;
    }

    const float* wp1 = W + 4 * jg;
    const float* hp1 = s1 + 8 * ug;
    const float* wp2 = W + K1 * CCH + 4 * jg;
    const float* hp2 = (K2 > 0) ? (s2 + 8 * ug) : hp1;

    // prime the pipeline
    float4  wn  = __ldg(reinterpret_cast<const float4*>(wp1));
    double2 hAn = *reinterpret_cast<const double2*>(hp1);
    double2 hBn = *reinterpret_cast<const double2*>(hp1 + 4);

#pragma unroll 4
    for (int k = 0; k < K1; ++k) {
        float4 wc = wn; double2 hAc = hAn, hBc = hBn;
        const float* wnx;
        const float* hnx;
        if (k + 1 < K1)      { wnx = wp1 + (k + 1) * CCH; hnx = hp1 + (k + 1) * PAD; }
        else if (K2 > 0)     { wnx = wp2;                 hnx = hp2; }
        else                 { wnx = wp1;                 hnx = hp1; }
        wn  = __ldg(reinterpret_cast<const float4*>(wnx));
        hAn = *reinterpret_cast<const double2*>(hnx);
        hBn = *reinterpret_cast<const double2*>(hnx + 4);
        kcompute(wc, hAc, hBc, acc);
    }
    if (K2 > 0) {
#pragma unroll 2
        for (int k = 0; k < K2; ++k) {
            float4 wc = wn; double2 hAc = hAn, hBc = hBn;
            int kn = (k + 1 < K2) ? (k + 1) : k;
            wn  = __ldg(reinterpret_cast<const float4*>(wp2 + kn * CCH));
            hAn = *reinterpret_cast<const double2*>(hp2 + kn * PAD);
            hBn = *reinterpret_cast<const double2*>(hp2 + kn * PAD + 4);
            kcompute(wc, hAc, hBc, acc);
        }
    }

#pragma unroll
    for (int ch = 0; ch < 4; ++ch) {
        float x[8];
        unpack2(acc[ch][0], x[0], x[1]);
        unpack2(acc[ch][1], x[2], x[3]);
        unpack2(acc[ch][2], x[4], x[5]);
        unpack2(acc[ch][3], x[6], x[7]);
        float4 oA, oB;
        oA.x = silu_f(x[0]); oA.y = silu_f(x[1]); oA.z = silu_f(x[2]); oA.w = silu_f(x[3]);
        oB.x = silu_f(x[4]); oB.y = silu_f(x[5]); oB.z = silu_f(x[6]); oB.w = silu_f(x[7]);
        int off = (4 * jg + ch) * PAD + 8 * ug;
        if (RES) {
            float4 rA = *reinterpret_cast<const float4*>(resid + off);
            float4 rB = *reinterpret_cast<const float4*>(resid + off + 4);
            oA.x += rA.x; oA.y += rA.y; oA.z += rA.z; oA.w += rA.w;
            oB.x += rB.x; oB.y += rB.y; oB.z += rB.z; oB.w += rB.w;
        }
        *reinterpret_cast<float4*>(dst + off)     = oA;
        *reinterpret_cast<float4*>(dst + off + 4) = oB;
    }
}

// ---------------------------------------------------------------------------
// Main kernel: each block = 4 points x 8 corners = 32 units, 96 threads.
// ---------------------------------------------------------------------------
__global__ void __launch_bounds__(THREADS, 4)
decoder_kernel(const float* __restrict__ qw_g,
               const int* __restrict__ mask_g,
               const float* __restrict__ grid_g,
               const float* __restrict__ affine_g,
               const float* __restrict__ w00, const float* __restrict__ b00,
               const float* __restrict__ w01, const float* __restrict__ b01,
               const float* __restrict__ w02, const float* __restrict__ b02,
               const float* __restrict__ w10, const float* __restrict__ b10,
               const float* __restrict__ w11, const float* __restrict__ b11,
               const float* __restrict__ w12, const float* __restrict__ b12,
               const float* __restrict__ wpo, const float* __restrict__ bpo,
               float* __restrict__ out) {
    const int tid = threadIdx.x;
    const int pg0 = blockIdx.x * NP;         // first global point of group
    const int b   = pg0 >> 15;               // batch (groups never straddle)

    extern __shared__ float smem[];
    float* s_y = smem;                       // [96][PAD]
    float* s_a = s_y + CCH * PAD;            // [96][PAD]
    float* s_b = s_a + CCH * PAD;            // [96][PAD]
    float* s_c = s_b + CCH * PAD;            // [78][PAD]

    __shared__ float s_inv[12];              // rows 0..2 of inv(affine)
    __shared__ float s_qw[NP][3];
    __shared__ float s_sub[NP][3];
    __shared__ float s_mf[NP];
    __shared__ int   s_bot[NP][3];
    __shared__ int   s_voff[NU];
    __shared__ float s_cw[NU][3];
    __shared__ float s_wtri[NU];

    // --- phase 1: affine inverse (last row assumed [0,0,0,1]) ---
    if (tid == 0) {
        const float* A = affine_g + b * 16;
        float a00 = A[0], a01 = A[1], a02 = A[2],  t0 = A[3];
        float a10 = A[4], a11 = A[5], a12 = A[6],  t1 = A[7];
        float a20 = A[8], a21 = A[9], a22 = A[10], t2 = A[11];
        float c00 = a11 * a22 - a12 * a21;
        float c01 = a02 * a21 - a01 * a22;
        float c02 = a01 * a12 - a02 * a11;
        float det = a00 * c00 + a10 * c01 + a20 * c02;
        float id  = 1.0f / det;
        float i00 = c00 * id, i01 = c01 * id, i02 = c02 * id;
        float i10 = (a12 * a20 - a10 * a22) * id;
        float i11 = (a00 * a22 - a02 * a20) * id;
        float i12 = (a02 * a10 - a00 * a12) * id;
        float i20 = (a10 * a21 - a11 * a20) * id;
        float i21 = (a01 * a20 - a00 * a21) * id;
        float i22 = (a00 * a11 - a01 * a10) * id;
        s_inv[0] = i00; s_inv[1] = i01; s_inv[2]  = i02; s_inv[3]  = -(i00 * t0 + i01 * t1 + i02 * t2);
        s_inv[4] = i10; s_inv[5] = i11; s_inv[6]  = i12; s_inv[7]  = -(i10 * t0 + i11 * t1 + i12 * t2);
        s_inv[8] = i20; s_inv[9] = i21; s_inv[10] = i22; s_inv[11] = -(i20 * t0 + i21 * t1 + i22 * t2);
    }
    __syncthreads();

    // --- phase 2: per-point setup ---
    if (tid < NP) {
        int pg = pg0 + tid;
        float mf = (mask_g[pg] != 0) ? 1.0f : 0.0f;
        const float* qp = qw_g + (mf != 0.0f ? (long)pg * 3
                                             : ((long)b * NPTS + NPTS / 2) * 3);
        float q0 = qp[0], q1 = qp[1], q2 = qp[2];
        s_qw[tid][0] = q0; s_qw[tid][1] = q1; s_qw[tid][2] = q2;
        s_mf[tid] = mf;
#pragma unroll
        for (int r = 0; r < 3; ++r) {
            float qv = s_inv[r * 4 + 0] * q0 + s_inv[r * 4 + 1] * q1 +
                       s_inv[r * 4 + 2] * q2 + s_inv[r * 4 + 3];
            float fb = floorf(qv);
            s_bot[tid][r] = (int)fb;
            s_sub[tid][r] = qv - fb;
        }
    }
    __syncthreads();

    // --- phase 3: per-unit voxel offset, cw gather, trilinear weight ---
    if (tid < NU) {
        int pt = tid >> 3, c = tid & 7;
        int o0 = (c >> 2) & 1, o1 = (c >> 1) & 1, o2 = c & 1;
        int i0 = min(max(s_bot[pt][0] + o0, 0), G - 1);
        int i1 = min(max(s_bot[pt][1] + o1, 0), G - 1);
        int i2 = min(max(s_bot[pt][2] + o2, 0), G - 1);
        int sp = (i0 * G + i1) * G + i2;
        s_voff[tid] = (b * NPTS + sp) * CCH;
        const float* gp = grid_g + (long)(b * NPTS + sp) * 3;
        s_cw[tid][0] = gp[0]; s_cw[tid][1] = gp[1]; s_cw[tid][2] = gp[2];
        float ww0 = o0 ? s_sub[pt][0] : 1.0f - s_sub[pt][0];
        float ww1 = o1 ? s_sub[pt][1] : 1.0f - s_sub[pt][1];
        float ww2 = o2 ? s_sub[pt][2] : 1.0f - s_sub[pt][2];
        s_wtri[tid] = ww0 * ww1 * ww2;
    }
    __syncthreads();

    // --- phase 4: feature gather + coordinate encoding ---
#pragma unroll 8
    for (int u = 0; u < NU; ++u) {
        float mf = s_mf[u >> 3];
        s_y[tid * PAD + u] = g_cvt[s_voff[u] + tid] * mf;
    }
    // coord rows 0..5: cw, qw   (192 entries)
#pragma unroll
    for (int it = 0; it < 2; ++it) {
        int idx = tid + it * THREADS;        // < 192
        int u = idx / 6, r = idx % 6;
        float mf = s_mf[u >> 3];
        float v = (r < 3) ? s_cw[u][r] : s_qw[u >> 3][r - 3];
        s_c[r * PAD + u] = v * mf;
    }
    // coord rows 6..77: fourier encoding (32 units x 3 axes x 12 freqs)
#pragma unroll
    for (int it = 0; it < 12; ++it) {
        int idx = tid + it * THREADS;        // < 1152
        int u = idx / 36, e = idx % 36;
        int a = e / 12, j = e % 12;
        int pt = u >> 3, c = u & 7;
        int off = (a == 0) ? ((c >> 2) & 1) : ((a == 1) ? ((c >> 1) & 1) : (c & 1));
        float rel = (s_sub[pt][a] - (float)off + 1.0f) * 0.5f;
        float f = exp2f((float)j * 0.13208020839342967f);   // 3^(j/12)
        float ang = 6.283185307179586f * f * rel;
        float sv, cv;
        __sincosf(ang, &sv, &cv);
        float mf = s_mf[pt];
        s_c[(6 + a * 24 + j) * PAD + u]      = sv * mf;
        s_c[(6 + a * 24 + 12 + j) * PAD + u] = cv * mf;
    }
    __syncthreads();

    // --- MLP: 2 x SkipMLPBlock ---
    const int jg = tid >> 2;   // channel group 0..23 (4 channels each)
    const int ug = tid & 3;    // unit group   0..3  (8 units each)

    mlp_layer<96, 78, false>(w00, b00, s_y, s_c, s_a, nullptr, jg, ug); __syncthreads();
    mlp_layer<96, 0,  false>(w01, b01, s_a, nullptr, s_b, nullptr, jg, ug); __syncthreads();
    mlp_layer<96, 0,  true >(w02, b02, s_b, nullptr, s_y, s_y,     jg, ug); __syncthreads();
    mlp_layer<96, 78, false>(w10, b10, s_y, s_c, s_a, nullptr, jg, ug); __syncthreads();
    mlp_layer<96, 0,  false>(w11, b11, s_a, nullptr, s_b, nullptr, jg, ug); __syncthreads();
    mlp_layer<96, 0,  true >(w12, b12, s_b, nullptr, s_y, s_y,     jg, ug); __syncthreads();

    // --- trilinear reduce across the 8 corners: ybar = sum_c wtri_c * y_c ---
    // (sum_c wtri_c == 1, so the post-GEMM applies once per point)
#pragma unroll
    for (int it = 0; it < 4; ++it) {
        int idx = tid + it * THREADS;        // < 384
        int ch = idx >> 2, pt = idx & 3;
        float acc = 0.0f;
#pragma unroll
        for (int c = 0; c < 8; ++c)
            acc += s_wtri[pt * 8 + c] * s_y[ch * PAD + pt * 8 + c];
        s_a[ch * PAD + pt] = acc;
    }
    __syncthreads();

    // --- post layer: 96 -> 45, 4 points ---
    if (tid < OUTC) {
        float a0 = bpo[tid], a1 = a0, a2 = a0, a3 = a0;
#pragma unroll 4
        for (int k = 0; k < CCH; ++k) {
            float w = __ldg(wpo + k * OUTC + tid);
            a0 = fmaf(s_a[k * PAD + 0], w, a0);
            a1 = fmaf(s_a[k * PAD + 1], w, a1);
            a2 = fmaf(s_a[k * PAD + 2], w, a2);
            a3 = fmaf(s_a[k * PAD + 3], w, a3);
        }
        int n0 = pg0 & (NPTS - 1);
        long base = ((long)b * OUTC + tid) * NPTS + n0;
        out[base]     = a0;
        out[base + 1] = a1;
        out[base + 2] = a2;
        out[base + 3] = a3;
    }
}

// ---------------------------------------------------------------------------
extern "C" void kernel_launch(void* const* d_in, const int* in_sizes, int n_in,
                              void* d_out, int out_size) {
    const float* context_v = (const float*)d_in[0];
    const float* grid      = (const float*)d_in[1];
    const float* qw        = (const float*)d_in[2];
    const int*   mask      = (const int*)d_in[3];
    const float* affine    = (const float*)d_in[4];
    const float* w00 = (const float*)d_in[8],  *b00 = (const float*)d_in[9];
    const float* w01 = (const float*)d_in[10], *b01 = (const float*)d_in[11];
    const float* w02 = (const float*)d_in[12], *b02 = (const float*)d_in[13];
    const float* w10 = (const float*)d_in[14], *b10 = (const float*)d_in[15];
    const float* w11 = (const float*)d_in[16], *b11 = (const float*)d_in[17];
    const float* w12 = (const float*)d_in[18], *b12 = (const float*)d_in[19];
    const float* wpo = (const float*)d_in[20], *bpo = (const float*)d_in[21];
    float* out = (float*)d_out;

    const int smem_bytes = (CCH * 3 + NCOORD) * PAD * sizeof(float);  // 52704
    static int configured = 0;
    if (!configured) {
        cudaFuncSetAttribute(decoder_kernel,
                             cudaFuncAttributeMaxDynamicSharedMemorySize,
                             smem_bytes);
        configured = 1;
    }

    transpose_ctx<<<NBATCH * 512, 256>>>(context_v);

    // 65536 points total, 4 points (32 point-corner units) per block
    decoder_kernel<<<(NBATCH * NPTS) / NP, THREADS, smem_bytes>>>(
        qw, mask, grid, affine,
        w00, b00, w01, b01, w02, b02,
        w10, b10, w11, b11, w12, b12,
        wpo, bpo, out);
}

// round 6
// speedup vs baseline: 1.0465x; 1.0465x over previous
#include <cuda_runtime.h>
#include <cstdint>

// ----------------------------------------------------------------------------
// Decoder_61237643706389 — fused trilinear MLP decoder, fp32x2 (FFMA2) path.
// Round 6: NP=4 shape (32 units, 96 threads, 12 warps/SM) with a CLEAN
// distance-2 software pipeline: constant-stride pointers, no per-iteration
// selects (r5's selects blew alu to 18% and broke the prefetch distance).
// ----------------------------------------------------------------------------

#define G        32
#define NBATCH   2
#define CCH      96
#define NPTS     32768          // points per batch (32^3)
#define OUTC     45
#define NCOORD   78
#define NP       4              // points per block
#define NU       32             // units per block (NP * 8 corners)
#define PAD      36             // row stride in floats (32 units + 4 pad, 144B)
#define THREADS  96

// Transposed context features: [B][x][y][z][C], contiguous C — 25.2 MB scratch.
__device__ float g_cvt[NBATCH * NPTS * CCH];

typedef unsigned long long u64;

__device__ __forceinline__ u64 pack2(float lo, float hi) {
    u64 r; asm("mov.b64 %0, {%1, %2};" : "=l"(r) : "f"(lo), "f"(hi)); return r;
}
__device__ __forceinline__ void unpack2(u64 v, float& lo, float& hi) {
    asm("mov.b64 {%0, %1}, %2;" : "=f"(lo), "=f"(hi) : "l"(v));
}
__device__ __forceinline__ u64 ffma2(u64 a, u64 b, u64 c) {
    u64 d; asm("fma.rn.f32x2 %0, %1, %2, %3;" : "=l"(d) : "l"(a), "l"(b), "l"(c));
    return d;
}
__device__ __forceinline__ float silu_f(float x) {
    return x / (1.0f + __expf(-x));
}

// ---------------------------------------------------------------------------
// Transpose context_v [B,C,S] -> g_cvt [B,S,C], S = 32^3. Tiled via SMEM.
// ---------------------------------------------------------------------------
__global__ void transpose_ctx(const float* __restrict__ src) {
    __shared__ float tile[CCH][65];          // pad 64->65 kills bank conflicts
    int bs = blockIdx.x;                     // 0 .. NBATCH*512-1
    int b  = bs >> 9;
    int s0 = (bs & 511) * 64;
    for (int idx = threadIdx.x; idx < CCH * 64; idx += blockDim.x) {
        int c = idx >> 6, so = idx & 63;
        tile[c][so] = src[((long)(b * CCH + c) << 15) + s0 + so];
    }
    __syncthreads();
    for (int idx = threadIdx.x; idx < CCH * 64; idx += blockDim.x) {
        int so = idx / CCH, c = idx % CCH;
        g_cvt[(((long)b << 15) + s0 + so) * CCH + c] = tile[c][so];
    }
}

// ---------------------------------------------------------------------------
// Compute one k-step from pre-loaded operands: 4 channels x 8 units = 16 FFMA2.
// ---------------------------------------------------------------------------
__device__ __forceinline__ void kcompute(float4 w4, double2 hA, double2 hB,
                                         u64 (&acc)[4][4]) {
    u64 h0 = __double_as_longlong(hA.x);
    u64 h1 = __double_as_longlong(hA.y);
    u64 h2 = __double_as_longlong(hB.x);
    u64 h3 = __double_as_longlong(hB.y);
    u64 wd;
    wd = pack2(w4.x, w4.x);
    acc[0][0] = ffma2(h0, wd, acc[0][0]); acc[0][1] = ffma2(h1, wd, acc[0][1]);
    acc[0][2] = ffma2(h2, wd, acc[0][2]); acc[0][3] = ffma2(h3, wd, acc[0][3]);
    wd = pack2(w4.y, w4.y);
    acc[1][0] = ffma2(h0, wd, acc[1][0]); acc[1][1] = ffma2(h1, wd, acc[1][1]);
    acc[1][2] = ffma2(h2, wd, acc[1][2]); acc[1][3] = ffma2(h3, wd, acc[1][3]);
    wd = pack2(w4.z, w4.z);
    acc[2][0] = ffma2(h0, wd, acc[2][0]); acc[2][1] = ffma2(h1, wd, acc[2][1]);
    acc[2][2] = ffma2(h2, wd, acc[2][2]); acc[2][3] = ffma2(h3, wd, acc[2][3]);
    wd = pack2(w4.w, w4.w);
    acc[3][0] = ffma2(h0, wd, acc[3][0]); acc[3][1] = ffma2(h1, wd, acc[3][1]);
    acc[3][2] = ffma2(h2, wd, acc[3][2]); acc[3][3] = ffma2(h3, wd, acc[3][3]);
}

// ---------------------------------------------------------------------------
// Distance-2 pipelined partial GEMM over one operand source.
// W points at thread's 4-channel column (row stride CCH), H at thread's
// 8-unit slice (row stride PAD). K must be even and >= 4.
// ---------------------------------------------------------------------------
template <int K>
__device__ __forceinline__ void gemm_part(const float* __restrict__ wp,
                                          const float* hp, u64 (&acc)[4][4]) {
    // prime two stages
    float4  w0  = __ldg(reinterpret_cast<const float4*>(wp));
    double2 hA0 = *reinterpret_cast<const double2*>(hp);
    double2 hB0 = *reinterpret_cast<const double2*>(hp + 4);
    wp += CCH; hp += PAD;
    float4  w1  = __ldg(reinterpret_cast<const float4*>(wp));
    double2 hA1 = *reinterpret_cast<const double2*>(hp);
    double2 hB1 = *reinterpret_cast<const double2*>(hp + 4);
    wp += CCH; hp += PAD;

#pragma unroll 2
    for (int k = 0; k < K - 2; k += 2) {
        float4  wn0  = __ldg(reinterpret_cast<const float4*>(wp));
        double2 hAn0 = *reinterpret_cast<const double2*>(hp);
        double2 hBn0 = *reinterpret_cast<const double2*>(hp + 4);
        wp += CCH; hp += PAD;
        kcompute(w0, hA0, hB0, acc);
        float4  wn1  = __ldg(reinterpret_cast<const float4*>(wp));
        double2 hAn1 = *reinterpret_cast<const double2*>(hp);
        double2 hBn1 = *reinterpret_cast<const double2*>(hp + 4);
        wp += CCH; hp += PAD;
        kcompute(w1, hA1, hB1, acc);
        w0 = wn0; hA0 = hAn0; hB0 = hBn0;
        w1 = wn1; hA1 = hAn1; hB1 = hBn1;
    }
    // drain
    kcompute(w0, hA0, hB0, acc);
    kcompute(w1, hA1, hB1, acc);
}

// Linear layer (K1 rows from s1, optional K2 rows from s2) + silu + residual.
// Activations layout: [96 channels][PAD units].
// Thread (jg, ug) owns channels 4jg..4jg+3, units 8ug..8ug+7.
template <int K1, int K2, bool RES>
__device__ __forceinline__ void mlp_layer(const float* __restrict__ W,
                                          const float* __restrict__ Bv,
                                          const float* s1, const float* s2,
                                          float* dst, const float* resid,
                                          int jg, int ug) {
    u64 acc[4][4];
#pragma unroll
    for (int ch = 0; ch < 4; ++ch) {
        float bv = __ldg(Bv + 4 * jg + ch);
        u64 bb = pack2(bv, bv);
        acc[ch][0] = bb; acc[ch][1] = bb; acc[ch][2] = bb; acc[ch][3] = bb;
    }

    gemm_part<K1>(W + 4 * jg, s1 + 8 * ug, acc);
    if (K2 > 0)
        gemm_part<(K2 > 0 ? K2 : 2)>(W + K1 * CCH + 4 * jg, s2 + 8 * ug, acc);

#pragma unroll
    for (int ch = 0; ch < 4; ++ch) {
        float x[8];
        unpack2(acc[ch][0], x[0], x[1]);
        unpack2(acc[ch][1], x[2], x[3]);
        unpack2(acc[ch][2], x[4], x[5]);
        unpack2(acc[ch][3], x[6], x[7]);
        float4 oA, oB;
        oA.x = silu_f(x[0]); oA.y = silu_f(x[1]); oA.z = silu_f(x[2]); oA.w = silu_f(x[3]);
        oB.x = silu_f(x[4]); oB.y = silu_f(x[5]); oB.z = silu_f(x[6]); oB.w = silu_f(x[7]);
        int off = (4 * jg + ch) * PAD + 8 * ug;
        if (RES) {
            float4 rA = *reinterpret_cast<const float4*>(resid + off);
            float4 rB = *reinterpret_cast<const float4*>(resid + off + 4);
            oA.x += rA.x; oA.y += rA.y; oA.z += rA.z; oA.w += rA.w;
            oB.x += rB.x; oB.y += rB.y; oB.z += rB.z; oB.w += rB.w;
        }
        *reinterpret_cast<float4*>(dst + off)     = oA;
        *reinterpret_cast<float4*>(dst + off + 4) = oB;
    }
}

// ---------------------------------------------------------------------------
// Main kernel: each block = 4 points x 8 corners = 32 units, 96 threads.
// ---------------------------------------------------------------------------
__global__ void __launch_bounds__(THREADS, 4)
decoder_kernel(const float* __restrict__ qw_g,
               const int* __restrict__ mask_g,
               const float* __restrict__ grid_g,
               const float* __restrict__ affine_g,
               const float* __restrict__ w00, const float* __restrict__ b00,
               const float* __restrict__ w01, const float* __restrict__ b01,
               const float* __restrict__ w02, const float* __restrict__ b02,
               const float* __restrict__ w10, const float* __restrict__ b10,
               const float* __restrict__ w11, const float* __restrict__ b11,
               const float* __restrict__ w12, const float* __restrict__ b12,
               const float* __restrict__ wpo, const float* __restrict__ bpo,
               float* __restrict__ out) {
    const int tid = threadIdx.x;
    const int pg0 = blockIdx.x * NP;         // first global point of group
    const int b   = pg0 >> 15;               // batch (groups never straddle)

    extern __shared__ float smem[];
    float* s_y = smem;                       // [96][PAD]
    float* s_a = s_y + CCH * PAD;            // [96][PAD]
    float* s_b = s_a + CCH * PAD;            // [96][PAD]
    float* s_c = s_b + CCH * PAD;            // [78][PAD]

    __shared__ float s_inv[12];              // rows 0..2 of inv(affine)
    __shared__ float s_qw[NP][3];
    __shared__ float s_sub[NP][3];
    __shared__ float s_mf[NP];
    __shared__ int   s_bot[NP][3];
    __shared__ int   s_voff[NU];
    __shared__ float s_cw[NU][3];
    __shared__ float s_wtri[NU];

    // --- phase 1: affine inverse (last row assumed [0,0,0,1]) ---
    if (tid == 0) {
        const float* A = affine_g + b * 16;
        float a00 = A[0], a01 = A[1], a02 = A[2],  t0 = A[3];
        float a10 = A[4], a11 = A[5], a12 = A[6],  t1 = A[7];
        float a20 = A[8], a21 = A[9], a22 = A[10], t2 = A[11];
        float c00 = a11 * a22 - a12 * a21;
        float c01 = a02 * a21 - a01 * a22;
        float c02 = a01 * a12 - a02 * a11;
        float det = a00 * c00 + a10 * c01 + a20 * c02;
        float id  = 1.0f / det;
        float i00 = c00 * id, i01 = c01 * id, i02 = c02 * id;
        float i10 = (a12 * a20 - a10 * a22) * id;
        float i11 = (a00 * a22 - a02 * a20) * id;
        float i12 = (a02 * a10 - a00 * a12) * id;
        float i20 = (a10 * a21 - a11 * a20) * id;
        float i21 = (a01 * a20 - a00 * a21) * id;
        float i22 = (a00 * a11 - a01 * a10) * id;
        s_inv[0] = i00; s_inv[1] = i01; s_inv[2]  = i02; s_inv[3]  = -(i00 * t0 + i01 * t1 + i02 * t2);
        s_inv[4] = i10; s_inv[5] = i11; s_inv[6]  = i12; s_inv[7]  = -(i10 * t0 + i11 * t1 + i12 * t2);
        s_inv[8] = i20; s_inv[9] = i21; s_inv[10] = i22; s_inv[11] = -(i20 * t0 + i21 * t1 + i22 * t2);
    }
    __syncthreads();

    // --- phase 2: per-point setup ---
    if (tid < NP) {
        int pg = pg0 + tid;
        float mf = (mask_g[pg] != 0) ? 1.0f : 0.0f;
        const float* qp = qw_g + (mf != 0.0f ? (long)pg * 3
                                             : ((long)b * NPTS + NPTS / 2) * 3);
        float q0 = qp[0], q1 = qp[1], q2 = qp[2];
        s_qw[tid][0] = q0; s_qw[tid][1] = q1; s_qw[tid][2] = q2;
        s_mf[tid] = mf;
#pragma unroll
        for (int r = 0; r < 3; ++r) {
            float qv = s_inv[r * 4 + 0] * q0 + s_inv[r * 4 + 1] * q1 +
                       s_inv[r * 4 + 2] * q2 + s_inv[r * 4 + 3];
            float fb = floorf(qv);
            s_bot[tid][r] = (int)fb;
            s_sub[tid][r] = qv - fb;
        }
    }
    __syncthreads();

    // --- phase 3: per-unit voxel offset, cw gather, trilinear weight ---
    if (tid < NU) {
        int pt = tid >> 3, c = tid & 7;
        int o0 = (c >> 2) & 1, o1 = (c >> 1) & 1, o2 = c & 1;
        int i0 = min(max(s_bot[pt][0] + o0, 0), G - 1);
        int i1 = min(max(s_bot[pt][1] + o1, 0), G - 1);
        int i2 = min(max(s_bot[pt][2] + o2, 0), G - 1);
        int sp = (i0 * G + i1) * G + i2;
        s_voff[tid] = (b * NPTS + sp) * CCH;
        const float* gp = grid_g + (long)(b * NPTS + sp) * 3;
        s_cw[tid][0] = gp[0]; s_cw[tid][1] = gp[1]; s_cw[tid][2] = gp[2];
        float ww0 = o0 ? s_sub[pt][0] : 1.0f - s_sub[pt][0];
        float ww1 = o1 ? s_sub[pt][1] : 1.0f - s_sub[pt][1];
        float ww2 = o2 ? s_sub[pt][2] : 1.0f - s_sub[pt][2];
        s_wtri[tid] = ww0 * ww1 * ww2;
    }
    __syncthreads();

    // --- phase 4: feature gather + coordinate encoding ---
#pragma unroll 8
    for (int u = 0; u < NU; ++u) {
        float mf = s_mf[u >> 3];
        s_y[tid * PAD + u] = g_cvt[s_voff[u] + tid] * mf;
    }
    // coord rows 0..5: cw, qw   (192 entries)
#pragma unroll
    for (int it = 0; it < 2; ++it) {
        int idx = tid + it * THREADS;        // < 192
        int u = idx / 6, r = idx % 6;
        float mf = s_mf[u >> 3];
        float v = (r < 3) ? s_cw[u][r] : s_qw[u >> 3][r - 3];
        s_c[r * PAD + u] = v * mf;
    }
    // coord rows 6..77: fourier encoding (32 units x 3 axes x 12 freqs)
#pragma unroll
    for (int it = 0; it < 12; ++it) {
        int idx = tid + it * THREADS;        // < 1152
        int u = idx / 36, e = idx % 36;
        int a = e / 12, j = e % 12;
        int pt = u >> 3, c = u & 7;
        int off = (a == 0) ? ((c >> 2) & 1) : ((a == 1) ? ((c >> 1) & 1) : (c & 1));
        float rel = (s_sub[pt][a] - (float)off + 1.0f) * 0.5f;
        float f = exp2f((float)j * 0.13208020839342967f);   // 3^(j/12)
        float ang = 6.283185307179586f * f * rel;
        float sv, cv;
        __sincosf(ang, &sv, &cv);
        float mf = s_mf[pt];
        s_c[(6 + a * 24 + j) * PAD + u]      = sv * mf;
        s_c[(6 + a * 24 + 12 + j) * PAD + u] = cv * mf;
    }
    __syncthreads();

    // --- MLP: 2 x SkipMLPBlock ---
    const int jg = tid >> 2;   // channel group 0..23 (4 channels each)
    const int ug = tid & 3;    // unit group   0..3  (8 units each)

    mlp_layer<96, 78, false>(w00, b00, s_y, s_c, s_a, nullptr, jg, ug); __syncthreads();
    mlp_layer<96, 0,  false>(w01, b01, s_a, nullptr, s_b, nullptr, jg, ug); __syncthreads();
    mlp_layer<96, 0,  true >(w02, b02, s_b, nullptr, s_y, s_y,     jg, ug); __syncthreads();
    mlp_layer<96, 78, false>(w10, b10, s_y, s_c, s_a, nullptr, jg, ug); __syncthreads();
    mlp_layer<96, 0,  false>(w11, b11, s_a, nullptr, s_b, nullptr, jg, ug); __syncthreads();
    mlp_layer<96, 0,  true >(w12, b12, s_b, nullptr, s_y, s_y,     jg, ug); __syncthreads();

    // --- trilinear reduce across the 8 corners: ybar = sum_c wtri_c * y_c ---
    // (sum_c wtri_c == 1, so the post-GEMM applies once per point)
#pragma unroll
    for (int it = 0; it < 4; ++it) {
        int idx = tid + it * THREADS;        // < 384
        int ch = idx >> 2, pt = idx & 3;
        float acc = 0.0f;
#pragma unroll
        for (int c = 0; c < 8; ++c)
            acc += s_wtri[pt * 8 + c] * s_y[ch * PAD + pt * 8 + c];
        s_a[ch * PAD + pt] = acc;
    }
    __syncthreads();

    // --- post layer: 96 -> 45, 4 points ---
    if (tid < OUTC) {
        float a0 = bpo[tid], a1 = a0, a2 = a0, a3 = a0;
#pragma unroll 4
        for (int k = 0; k < CCH; ++k) {
            float w = __ldg(wpo + k * OUTC + tid);
            a0 = fmaf(s_a[k * PAD + 0], w, a0);
            a1 = fmaf(s_a[k * PAD + 1], w, a1);
            a2 = fmaf(s_a[k * PAD + 2], w, a2);
            a3 = fmaf(s_a[k * PAD + 3], w, a3);
        }
        int n0 = pg0 & (NPTS - 1);
        long base = ((long)b * OUTC + tid) * NPTS + n0;
        out[base]     = a0;
        out[base + 1] = a1;
        out[base + 2] = a2;
        out[base + 3] = a3;
    }
}

// ---------------------------------------------------------------------------
extern "C" void kernel_launch(void* const* d_in, const int* in_sizes, int n_in,
                              void* d_out, int out_size) {
    const float* context_v = (const float*)d_in[0];
    const float* grid      = (const float*)d_in[1];
    const float* qw        = (const float*)d_in[2];
    const int*   mask      = (const int*)d_in[3];
    const float* affine    = (const float*)d_in[4];
    const float* w00 = (const float*)d_in[8],  *b00 = (const float*)d_in[9];
    const float* w01 = (const float*)d_in[10], *b01 = (const float*)d_in[11];
    const float* w02 = (const float*)d_in[12], *b02 = (const float*)d_in[13];
    const float* w10 = (const float*)d_in[14], *b10 = (const float*)d_in[15];
    const float* w11 = (const float*)d_in[16], *b11 = (const float*)d_in[17];
    const float* w12 = (const float*)d_in[18], *b12 = (const float*)d_in[19];
    const float* wpo = (const float*)d_in[20], *bpo = (const float*)d_in[21];
    float* out = (float*)d_out;

    const int smem_bytes = (CCH * 3 + NCOORD) * PAD * sizeof(float);  // 52704
    static int configured = 0;
    if (!configured) {
        cudaFuncSetAttribute(decoder_kernel,
                             cudaFuncAttributeMaxDynamicSharedMemorySize,
                             smem_bytes);
        configured = 1;
    }

    transpose_ctx<<<NBATCH * 512, 256>>>(context_v);

    // 65536 points total, 4 points (32 point-corner units) per block
    decoder_kernel<<<(NBATCH * NPTS) / NP, THREADS, smem_bytes>>>(
        qw, mask, grid, affine,
        w00, b00, w01, b01, w02, b02,
        w10, b10, w11, b11, w12, b12,
        wpo, bpo, out);
}